// round 11
// baseline (speedup 1.0000x reference)
#include <cuda_runtime.h>
#include <cuda_bf16.h>
#include <cstdint>

// ---------------------------------------------------------------------------
// W8A8B32O32 Linear: out[8192,4096] = x[8192,4096]i8 @ w[4096,4096]i8^T + bias
//
// R11: GEMM pinned at the ~10 TB/s L2 rate (2.1GB / 210us). Cut traffic 25%
// with cluster-2 (along M) B-tile MULTICAST: each rank bulk-loads half of B
// and multicasts to both CTAs; A unicast. free[] barriers become cluster-wide
// (count=2, multicast tcgen05.commit) for correct cross-CTA back-pressure.
// ---------------------------------------------------------------------------
#define TOKENS 8192
#define NDIM   4096
#define KDIM   4096

#define TM 256
#define TN 256
#define KC 64                     // K elems per chunk (128 B of bf16)
#define CHUNKS (KDIM / KC)        // 64
#define MT (TOKENS / TM)          // 32
#define NT (NDIM / TN)            // 16

#define A_TILE 32768              // 256 rows x 128 B
#define B_TILE 32768              // 256 rows x 128 B
#define B_HALF (B_TILE / 2)       // 16384
#define STAGE_BYTES (A_TILE + B_TILE)          // 65536
#define NSTAGE 3
#define TC_SMEM (2048 + NSTAGE * STAGE_BYTES)  // 198656

// Feature gate: arch-specific ('a'/family) device pass only.
#if defined(__CUDA_ARCH_FEAT_SM103_ALL) || defined(__CUDA_ARCH_FEAT_SM100_ALL) || \
    defined(__CUDA_ARCH_SPECIFIC__) || defined(__CUDA_ARCH_FAMILY_SPECIFIC__)
#define W8A8_TC 1
#else
#define W8A8_TC 0
#endif

#define SW128(off) ((off) ^ (((off) >> 3) & 0x70))

// ---- device scratch: pre-tiled, pre-swizzled bf16 operands ----
__device__ __align__(1024) uint8_t g_xt[(size_t)MT * CHUNKS * A_TILE];  // 64 MB
__device__ __align__(1024) uint8_t g_wt[(size_t)NT * CHUNKS * B_TILE];  // 32 MB
__device__ float g_bf[NDIM];

// ---------------------------------------------------------------------------
// convert: classify dtype, write bf16 pre-tiled scratch
// ---------------------------------------------------------------------------
__device__ int classify16(const uint32_t* p) {
    int fc = 0, ic = 0;
    for (int i = 0; i < 16; i++) {
        uint32_t u = p[i];
        if (((u >> 23) & 0xFF) != 0xFF) {
            float f = __uint_as_float(u);
            if (f == rintf(f) && fabsf(f) <= 4096.0f) fc++;
        }
        int v = (int)u;
        if (v >= -4096 && v <= 4096) ic++;
    }
    if (fc >= 12) return 2;   // float32
    if (ic >= 12) return 1;   // int32
    return 0;                 // packed int8
}

__device__ __forceinline__ void load8f(const void* src, size_t e0, int mode, float* f) {
    if (mode == 0) {
        uint2 r = *(const uint2*)((const int8_t*)src + e0);
        f[0] = (float)(int)(signed char)(r.x);
        f[1] = (float)(int)(signed char)(r.x >> 8);
        f[2] = (float)(int)(signed char)(r.x >> 16);
        f[3] = (float)(int)(signed char)(r.x >> 24);
        f[4] = (float)(int)(signed char)(r.y);
        f[5] = (float)(int)(signed char)(r.y >> 8);
        f[6] = (float)(int)(signed char)(r.y >> 16);
        f[7] = (float)(int)(signed char)(r.y >> 24);
    } else if (mode == 1) {
        int4 a = ((const int4*)src)[e0 / 4];
        int4 b = ((const int4*)src)[e0 / 4 + 1];
        f[0] = (float)a.x; f[1] = (float)a.y; f[2] = (float)a.z; f[3] = (float)a.w;
        f[4] = (float)b.x; f[5] = (float)b.y; f[6] = (float)b.z; f[7] = (float)b.w;
    } else {
        float4 a = ((const float4*)src)[e0 / 4];
        float4 b = ((const float4*)src)[e0 / 4 + 1];
        f[0] = a.x; f[1] = a.y; f[2] = a.z; f[3] = a.w;
        f[4] = b.x; f[5] = b.y; f[6] = b.z; f[7] = b.w;
    }
}

__global__ void convert_kernel(const void* xs, const void* ws, const void* bs) {
    __shared__ int smode[3];
    if (threadIdx.x == 0) {
        smode[0] = classify16((const uint32_t*)xs);
        smode[1] = classify16((const uint32_t*)ws);
        smode[2] = classify16((const uint32_t*)bs);
    }
    __syncthreads();
    const int xm = smode[0], wm = smode[1], bm = smode[2];

    const size_t stride = (size_t)gridDim.x * blockDim.x;
    const size_t t0 = (size_t)blockIdx.x * blockDim.x + threadIdx.x;

    union { uint4 v; __nv_bfloat16 h[8]; } u;
    float f[8];

    const size_t nsegA = (size_t)MT * CHUNKS * TM * 8;
    for (size_t i = t0; i < nsegA; i += stride) {
        const int seg = (int)(i & 7);
        const int row = (int)((i >> 3) & (TM - 1));
        const int t   = (int)(i >> 11);          // mt*64 + kc
        const int mt  = t >> 6, kc = t & 63;
        const size_t e0 = ((size_t)(mt * TM + row)) * KDIM + (size_t)kc * KC + seg * 8;
        load8f(xs, e0, xm, f);
        #pragma unroll
        for (int j = 0; j < 8; j++) u.h[j] = __float2bfloat16_rn(f[j]);
        *(uint4*)(g_xt + ((size_t)t << 15) + SW128((uint32_t)(row * 128 + seg * 16))) = u.v;
    }

    const size_t nsegB = (size_t)NT * CHUNKS * TN * 8;
    for (size_t i = t0; i < nsegB; i += stride) {
        const int seg = (int)(i & 7);
        const int row = (int)((i >> 3) & (TN - 1));
        const int t   = (int)(i >> 11);          // nt*64 + kc
        const int nt  = t >> 6, kc = t & 63;
        const size_t e0 = ((size_t)(nt * TN + row)) * KDIM + (size_t)kc * KC + seg * 8;
        load8f(ws, e0, wm, f);
        #pragma unroll
        for (int j = 0; j < 8; j++) u.h[j] = __float2bfloat16_rn(f[j]);
        *(uint4*)(g_wt + ((size_t)t << 15) + SW128((uint32_t)(row * 128 + seg * 16))) = u.v;
    }

    for (size_t i = t0; i < NDIM; i += stride) {
        if (bm == 2) g_bf[i] = ((const float*)bs)[i];
        else         g_bf[i] = (float)((const int*)bs)[i];
    }
}

// ---------------------------------------------------------------------------
// tcgen05 machinery (arch-specific pass only)
// ---------------------------------------------------------------------------
__device__ __forceinline__ uint32_t smem_u32(const void* p) {
    uint32_t a;
    asm("{ .reg .u64 t; cvta.to.shared.u64 t, %1; cvt.u32.u64 %0, t; }"
        : "=r"(a) : "l"(p));
    return a;
}

#if W8A8_TC
static constexpr uint32_t TC_IDESC =
    (1u << 4) | (1u << 7) | (1u << 10) | ((TN / 8) << 17) | ((128u / 16) << 24);

static constexpr uint64_t SMEM_DESC_BASE_SW128 =
    (uint64_t(2) << 61) | (uint64_t(1) << 46) | (uint64_t(64) << 32) | (uint64_t(1) << 16);
#define MAKE_SMEM_DESC(base_addr) \
    (SMEM_DESC_BASE_SW128 | ((uint64_t)((base_addr) >> 4) & 0x3FFF))

__device__ __forceinline__ void tc_mma_bf16(uint32_t d_tmem, uint64_t a_desc,
                                            uint64_t b_desc, uint32_t idesc, bool acc) {
    uint32_t en = acc ? 1u : 0u;
    asm volatile(
        "{ .reg .pred p; setp.ne.u32 p, %5, 0;\n\t"
        "tcgen05.mma.cta_group::1.kind::f16 [%0], %1, %2, %3, {%4, %4, %4, %4}, p; }"
        :: "r"(d_tmem), "l"(a_desc), "l"(b_desc), "r"(idesc), "r"(0u), "r"(en)
        : "memory");
}
__device__ __forceinline__ void bulk_g2s(uint32_t dst, const void* src,
                                         uint32_t bytes, uint32_t mbar) {
    asm volatile(
        "cp.async.bulk.shared::cta.global.mbarrier::complete_tx::bytes [%0], [%1], %2, [%3];"
        :: "r"(dst), "l"(src), "r"(bytes), "r"(mbar) : "memory");
}
__device__ __forceinline__ void bulk_g2s_mcast(uint32_t dst, const void* src,
                                               uint32_t bytes, uint32_t mbar,
                                               uint16_t mask) {
    asm volatile(
        "cp.async.bulk.shared::cluster.global.mbarrier::complete_tx::bytes.multicast::cluster "
        "[%0], [%1], %2, [%3], %4;"
        :: "r"(dst), "l"(src), "r"(bytes), "r"(mbar), "h"(mask) : "memory");
}
__device__ __forceinline__ uint32_t cluster_rank() {
    uint32_t r;
    asm("mov.u32 %0, %%cluster_ctarank;" : "=r"(r));
    return r;
}
#define TC_ALLOC(smem_addr, n) \
    asm volatile("tcgen05.alloc.cta_group::1.sync.aligned.shared::cta.b32 [%0], %1;" \
                 :: "r"((uint32_t)(smem_addr)), "r"((uint32_t)(n)) : "memory")
#define TC_DEALLOC(tmem, n) \
    asm volatile("tcgen05.dealloc.cta_group::1.sync.aligned.b32 %0, %1;" \
                 :: "r"(tmem), "r"((uint32_t)(n)))
#define TC_COMMIT(mbar) \
    asm volatile("tcgen05.commit.cta_group::1.mbarrier::arrive::one.shared::cluster.b64 [%0];" \
                 :: "r"((uint32_t)(mbar)) : "memory")
#define TC_COMMIT_MCAST(mbar, mask) \
    asm volatile("tcgen05.commit.cta_group::1.mbarrier::arrive::one.shared::cluster.multicast::cluster.b64 [%0], %1;" \
                 :: "r"((uint32_t)(mbar)), "h"((uint16_t)(mask)) : "memory")
#define TC_FENCE_AFTER()  asm volatile("tcgen05.fence::after_thread_sync;" ::: "memory")
#define TC_FENCE_BEFORE() asm volatile("tcgen05.fence::before_thread_sync;" ::: "memory")
#define TC_WAIT_LD()      asm volatile("tcgen05.wait::ld.sync.aligned;" ::: "memory")
#define TC_LD_X32(r, addr) \
    asm volatile("tcgen05.ld.sync.aligned.32x32b.x32.b32 " \
        "{%0, %1, %2, %3, %4, %5, %6, %7, %8, %9, %10, %11, %12, %13, %14, %15, " \
        " %16, %17, %18, %19, %20, %21, %22, %23, %24, %25, %26, %27, %28, %29, %30, %31}, [%32];" \
        : "=r"((r)[0]), "=r"((r)[1]), "=r"((r)[2]), "=r"((r)[3]), \
          "=r"((r)[4]), "=r"((r)[5]), "=r"((r)[6]), "=r"((r)[7]), \
          "=r"((r)[8]), "=r"((r)[9]), "=r"((r)[10]), "=r"((r)[11]), \
          "=r"((r)[12]), "=r"((r)[13]), "=r"((r)[14]), "=r"((r)[15]), \
          "=r"((r)[16]), "=r"((r)[17]), "=r"((r)[18]), "=r"((r)[19]), \
          "=r"((r)[20]), "=r"((r)[21]), "=r"((r)[22]), "=r"((r)[23]), \
          "=r"((r)[24]), "=r"((r)[25]), "=r"((r)[26]), "=r"((r)[27]), \
          "=r"((r)[28]), "=r"((r)[29]), "=r"((r)[30]), "=r"((r)[31]) \
        : "r"(addr))
#define MBAR_INIT(mbar, n) \
    asm volatile("mbarrier.init.shared.b64 [%0], %1;" \
                 :: "r"((uint32_t)(mbar)), "r"((uint32_t)(n)) : "memory")
#define MBAR_EXPECT_TX(mbar, bytes) \
    asm volatile("mbarrier.arrive.expect_tx.shared.b64 _, [%0], %1;" \
                 :: "r"((uint32_t)(mbar)), "r"((uint32_t)(bytes)) : "memory")
#define MBAR_INVAL(mbar) \
    asm volatile("mbarrier.inval.shared.b64 [%0];" :: "r"((uint32_t)(mbar)) : "memory")
#define MBAR_WAIT(mbar, parity) do { \
    uint32_t _m = (uint32_t)(mbar), _p = (uint32_t)(parity), _d; \
    asm volatile("{ .reg .pred p; mbarrier.try_wait.parity.acquire.cta.shared::cta.b64 p, [%1], %2; selp.b32 %0, 1, 0, p; }" \
                 : "=r"(_d) : "r"(_m), "r"(_p) : "memory"); \
    if (!_d) { \
        asm volatile("{ .reg .pred P1;\n\tWL_%=:\n\t" \
            "mbarrier.try_wait.parity.acquire.cta.shared::cta.b64 P1, [%0], %1, 0x989680;\n\t" \
            "@P1 bra.uni WD_%=;\n\tbra.uni WL_%=;\n\tWD_%=:\n\t}" \
            :: "r"(_m), "r"(_p) : "memory"); \
    } \
} while (0)
#define FENCE_PROXY() asm volatile("fence.proxy.async.shared::cta;" ::: "memory")
#define CLUSTER_SYNC() do { \
    asm volatile("barrier.cluster.arrive.aligned;" ::: "memory"); \
    asm volatile("barrier.cluster.wait.aligned;" ::: "memory"); \
} while (0)
#endif  // W8A8_TC

__global__ __launch_bounds__(256, 1) __cluster_dims__(1, 2, 1)
void w8a8_tc_kernel(float* __restrict__ out)
{
#if W8A8_TC
    extern __shared__ char dsm[];
    const uint32_t raw   = smem_u32(dsm);
    const uint32_t hdr   = (raw + 1023u) & ~1023u;   // [hdr]=tmem ptr
    const uint32_t full0 = hdr + 16;                 // full[s] = +16+8s  (3)
    const uint32_t free0 = hdr + 48;                 // free[s] = +48+8s  (3)
    const uint32_t fin   = hdr + 96;
    const uint32_t tiles = hdr + 1024;

    const int tid  = threadIdx.x;
    const int wid  = tid >> 5;
    const int lane = tid & 31;
    const int nt = blockIdx.x;              // 0..15  (B tile, shared in pair)
    const int mt = blockIdx.y;              // 0..31  (A tile, per CTA)
    const uint32_t rank = cluster_rank();   // 0/1 within M-pair

    if (wid == 0) TC_ALLOC(hdr, 512);
    if (tid == 0) {
        #pragma unroll
        for (int s = 0; s < NSTAGE; s++) {
            MBAR_INIT(full0 + 8 * s, 1);   // 1 arrive: own expect_tx
            MBAR_INIT(free0 + 8 * s, 2);   // 2 arrives: both consumers' commits
        }
        MBAR_INIT(fin, 1);
    }
    __syncthreads();
    FENCE_PROXY();
    CLUSTER_SYNC();   // peer barriers initialized before any multicast lands
    uint32_t tmem;
    asm volatile("ld.shared.b32 %0, [%1];" : "=r"(tmem) : "r"(hdr));

    const uint8_t* a_src = g_xt + ((size_t)(mt * CHUNKS) << 15);
    const uint8_t* b_src = g_wt + ((size_t)(nt * CHUNKS) << 15) + rank * B_HALF;

    if (tid == 0) {
        // ---- producer: A unicast, own B-half multicast to both CTAs ----
        for (int kc = 0; kc < CHUNKS; kc++) {
            const int s = kc % NSTAGE;
            const int i = kc / NSTAGE;
            if (kc >= NSTAGE) MBAR_WAIT(free0 + 8 * s, (i - 1) & 1);
            MBAR_EXPECT_TX(full0 + 8 * s, STAGE_BYTES);
            bulk_g2s(tiles + s * STAGE_BYTES, a_src + ((size_t)kc << 15),
                     A_TILE, full0 + 8 * s);
            bulk_g2s_mcast(tiles + s * STAGE_BYTES + A_TILE + rank * B_HALF,
                           b_src + ((size_t)kc << 15),
                           B_HALF, full0 + 8 * s, 0x3);
        }
    } else if (tid == 32) {
        // ---- consumer: two M=128 dispatches per k-step ----
        for (int kc = 0; kc < CHUNKS; kc++) {
            const int s = kc % NSTAGE;
            const int i = kc / NSTAGE;
            MBAR_WAIT(full0 + 8 * s, i & 1);
            const uint64_t a0 = MAKE_SMEM_DESC(tiles + s * STAGE_BYTES);
            const uint64_t a1 = MAKE_SMEM_DESC(tiles + s * STAGE_BYTES + A_TILE / 2);
            const uint64_t bd = MAKE_SMEM_DESC(tiles + s * STAGE_BYTES + A_TILE);
            const bool accb = (kc > 0);
            #pragma unroll
            for (int st = 0; st < 4; st++) {   // K=16 per MMA, +32B = +2 desc units
                tc_mma_bf16(tmem,       a0 + st * 2, bd + st * 2, TC_IDESC, accb || (st > 0));
                tc_mma_bf16(tmem + 256, a1 + st * 2, bd + st * 2, TC_IDESC, accb || (st > 0));
            }
            // release stage s in BOTH CTAs once these MMAs retire
            TC_COMMIT_MCAST(free0 + 8 * s, 0x3);
        }
        TC_COMMIT(fin);
    }

    // ---- all threads: wait for final MMA, then epilogue ----
    MBAR_WAIT(fin, 0);
    TC_FENCE_AFTER();

    {
        const int sub  = wid & 3;              // TMEM subpartition
        const int half = wid >> 2;             // 0: M rows 0-127, 1: rows 128-255
        const int row  = mt * TM + half * 128 + sub * 32 + lane;
        float* orow = out + (size_t)row * NDIM + nt * TN;
        const float* bb = g_bf + nt * TN;
        const uint32_t tbase = tmem + half * 256;

        #pragma unroll
        for (int q = 0; q < 8; q++) {
            uint32_t d[32];
            TC_LD_X32(d, tbase + q * 32);
            TC_WAIT_LD();
            #pragma unroll
            for (int j = 0; j < 8; j++) {
                float4 bj = *(const float4*)(bb + q * 32 + j * 4);
                float4 v;
                v.x = __uint_as_float(d[j * 4 + 0]) + bj.x;
                v.y = __uint_as_float(d[j * 4 + 1]) + bj.y;
                v.z = __uint_as_float(d[j * 4 + 2]) + bj.z;
                v.w = __uint_as_float(d[j * 4 + 3]) + bj.w;
                *(float4*)(orow + q * 32 + j * 4) = v;
            }
        }
        TC_FENCE_BEFORE();
    }

    __syncthreads();
    CLUSTER_SYNC();   // peer's multicast commits/copies fully drained
    if (tid == 0) {
        #pragma unroll
        for (int s = 0; s < NSTAGE; s++) {
            MBAR_INVAL(full0 + 8 * s);
            MBAR_INVAL(free0 + 8 * s);
        }
        MBAR_INVAL(fin);
    }
    __syncthreads();
    if (wid == 0) TC_DEALLOC(tmem, 512);
    CLUSTER_SYNC();
#endif  // W8A8_TC
}

// ---------------------------------------------------------------------------
// Launch wrapper: bind by relative size (x > weight > bias); 2 launches.
// ---------------------------------------------------------------------------
extern "C" void kernel_launch(void* const* d_in, const int* in_sizes, int n_in,
                              void* d_out, int out_size)
{
    int idx[3] = {0, 1, 2};
    if (n_in >= 3) {
        for (int a = 0; a < 3; a++)
            for (int b2 = a + 1; b2 < 3; b2++)
                if ((long)in_sizes[idx[b2]] > (long)in_sizes[idx[a]]) {
                    int t = idx[a]; idx[a] = idx[b2]; idx[b2] = t;
                }
    }
    const void* x = d_in[idx[0]];
    const void* w = d_in[idx[1]];
    const void* b = d_in[idx[2]];
    float* out = (float*)d_out;
    (void)out_size;

    cudaFuncSetAttribute(w8a8_tc_kernel,
                         cudaFuncAttributeMaxDynamicSharedMemorySize, TC_SMEM);

    convert_kernel<<<2048, 256>>>(x, w, b);

    dim3 grid(NT, MT);   // (16, 32) = 512 CTAs, clusters of 2 along y
    w8a8_tc_kernel<<<grid, 256, TC_SMEM>>>(out);
}

// round 12
// speedup vs baseline: 1.0456x; 1.0456x over previous
#include <cuda_runtime.h>
#include <cuda_bf16.h>
#include <cstdint>

// ---------------------------------------------------------------------------
// W8A8B32O32 Linear: out[8192,4096] = x[8192,4096]i8 @ w[4096,4096]i8^T + bias
//
// R12: cg2 (cta_group::2) pair-MMA, pair tile 256(M) x 512(N).
//  - A M-split, B N-split across the 2 CTAs (test_2cta_mma pattern)
//  - per CTA per K-chunk: 48KB -> 0.75 B/output, 1.57GB total L2 traffic
//  - local producers + rank1 relay (mapa arrive) -> rank0 consumer,
//    cg2 multicast commit releases both CTAs' stage barriers. NSTAGE=4.
// ---------------------------------------------------------------------------
#define TOKENS 8192
#define NDIM   4096
#define KDIM   4096

#define KC 64                     // K elems per chunk (128 B bf16)
#define CHUNKS (KDIM / KC)        // 64
#define PAIR_M 256
#define PAIR_N 512
#define MT (TOKENS / PAIR_M)      // 32
#define NT8 (NDIM / PAIR_N)       // 8

#define A_CH 16384                // 128 rows x 128 B per CTA per chunk
#define B_CH 32768                // 256 rows (2 N-halves) per CTA per chunk
#define STAGE_BYTES (A_CH + B_CH) // 49152
#define NSTAGE 4
#define TC_SMEM (2048 + NSTAGE * STAGE_BYTES)  // 198656

#if defined(__CUDA_ARCH_FEAT_SM103_ALL) || defined(__CUDA_ARCH_FEAT_SM100_ALL) || \
    defined(__CUDA_ARCH_SPECIFIC__) || defined(__CUDA_ARCH_FAMILY_SPECIFIC__)
#define W8A8_TC 1
#else
#define W8A8_TC 0
#endif

#define SW128(off) ((off) ^ (((off) >> 3) & 0x70))

// ---- device scratch: pre-tiled, pre-swizzled bf16 operands ----
// A: [mt2(64)][kc(64)] 16KB tiles (128 rows), mt2 = mt*2 + rank
// B: [nt8(8)][kc(64)] 64KB tiles: [rank(2)][half(2)][row(128)][128B]
//    global n = nt8*512 + half*256 + rank*128 + row
__device__ __align__(1024) uint8_t g_xt[(size_t)64 * CHUNKS * A_CH];    // 64 MB
__device__ __align__(1024) uint8_t g_wt[(size_t)NT8 * CHUNKS * 65536];  // 32 MB
__device__ float g_bf[NDIM];

// ---------------------------------------------------------------------------
// convert: classify dtype, write bf16 pre-tiled scratch
// ---------------------------------------------------------------------------
__device__ int classify16(const uint32_t* p) {
    int fc = 0, ic = 0;
    for (int i = 0; i < 16; i++) {
        uint32_t u = p[i];
        if (((u >> 23) & 0xFF) != 0xFF) {
            float f = __uint_as_float(u);
            if (f == rintf(f) && fabsf(f) <= 4096.0f) fc++;
        }
        int v = (int)u;
        if (v >= -4096 && v <= 4096) ic++;
    }
    if (fc >= 12) return 2;   // float32
    if (ic >= 12) return 1;   // int32
    return 0;                 // packed int8
}

__device__ __forceinline__ void load8f(const void* src, size_t e0, int mode, float* f) {
    if (mode == 0) {
        uint2 r = *(const uint2*)((const int8_t*)src + e0);
        f[0] = (float)(int)(signed char)(r.x);
        f[1] = (float)(int)(signed char)(r.x >> 8);
        f[2] = (float)(int)(signed char)(r.x >> 16);
        f[3] = (float)(int)(signed char)(r.x >> 24);
        f[4] = (float)(int)(signed char)(r.y);
        f[5] = (float)(int)(signed char)(r.y >> 8);
        f[6] = (float)(int)(signed char)(r.y >> 16);
        f[7] = (float)(int)(signed char)(r.y >> 24);
    } else if (mode == 1) {
        int4 a = ((const int4*)src)[e0 / 4];
        int4 b = ((const int4*)src)[e0 / 4 + 1];
        f[0] = (float)a.x; f[1] = (float)a.y; f[2] = (float)a.z; f[3] = (float)a.w;
        f[4] = (float)b.x; f[5] = (float)b.y; f[6] = (float)b.z; f[7] = (float)b.w;
    } else {
        float4 a = ((const float4*)src)[e0 / 4];
        float4 b = ((const float4*)src)[e0 / 4 + 1];
        f[0] = a.x; f[1] = a.y; f[2] = a.z; f[3] = a.w;
        f[4] = b.x; f[5] = b.y; f[6] = b.z; f[7] = b.w;
    }
}

__global__ void convert_kernel(const void* xs, const void* ws, const void* bs) {
    __shared__ int smode[3];
    if (threadIdx.x == 0) {
        smode[0] = classify16((const uint32_t*)xs);
        smode[1] = classify16((const uint32_t*)ws);
        smode[2] = classify16((const uint32_t*)bs);
    }
    __syncthreads();
    const int xm = smode[0], wm = smode[1], bm = smode[2];

    const size_t stride = (size_t)gridDim.x * blockDim.x;
    const size_t t0 = (size_t)blockIdx.x * blockDim.x + threadIdx.x;

    union { uint4 v; __nv_bfloat16 h[8]; } u;
    float f[8];

    // A: 64 mt2 * 64 kc * 128 rows * 8 segs
    const size_t nsegA = (size_t)64 * CHUNKS * 128 * 8;
    for (size_t i = t0; i < nsegA; i += stride) {
        const int seg = (int)(i & 7);
        const int row = (int)((i >> 3) & 127);
        const int t   = (int)(i >> 10);          // mt2*64 + kc
        const int mt2 = t >> 6, kc = t & 63;
        const size_t e0 = ((size_t)(mt2 * 128 + row)) * KDIM + (size_t)kc * KC + seg * 8;
        load8f(xs, e0, xm, f);
        #pragma unroll
        for (int j = 0; j < 8; j++) u.h[j] = __float2bfloat16_rn(f[j]);
        *(uint4*)(g_xt + ((size_t)t << 14) + SW128((uint32_t)(row * 128 + seg * 16))) = u.v;
    }

    // B: 8 nt8 * 64 kc * 2 rank * 2 half * 128 rows * 8 segs
    const size_t nsegB = (size_t)NT8 * CHUNKS * 2 * 2 * 128 * 8;
    for (size_t i = t0; i < nsegB; i += stride) {
        const int seg  = (int)(i & 7);
        const int row  = (int)((i >> 3) & 127);
        const int half = (int)((i >> 10) & 1);
        const int rank = (int)((i >> 11) & 1);
        const int t    = (int)(i >> 12);         // nt8*64 + kc
        const int nt8  = t >> 6, kc = t & 63;
        const int n = nt8 * 512 + half * 256 + rank * 128 + row;
        const size_t e0 = (size_t)n * KDIM + (size_t)kc * KC + seg * 8;
        load8f(ws, e0, wm, f);
        #pragma unroll
        for (int j = 0; j < 8; j++) u.h[j] = __float2bfloat16_rn(f[j]);
        *(uint4*)(g_wt + ((size_t)t << 16) + ((uint32_t)rank << 15) + ((uint32_t)half << 14)
                  + SW128((uint32_t)(row * 128 + seg * 16))) = u.v;
    }

    for (size_t i = t0; i < NDIM; i += stride) {
        if (bm == 2) g_bf[i] = ((const float*)bs)[i];
        else         g_bf[i] = (float)((const int*)bs)[i];
    }
}

// ---------------------------------------------------------------------------
// tcgen05 machinery (arch-specific pass only)
// ---------------------------------------------------------------------------
__device__ __forceinline__ uint32_t smem_u32(const void* p) {
    uint32_t a;
    asm("{ .reg .u64 t; cvta.to.shared.u64 t, %1; cvt.u32.u64 %0, t; }"
        : "=r"(a) : "l"(p));
    return a;
}

#if W8A8_TC
// idesc kind::f16 cg2: dtype F32, a/b BF16, N=256 per dispatch, M_TOTAL=256
static constexpr uint32_t TC_IDESC =
    (1u << 4) | (1u << 7) | (1u << 10) | ((256u / 8) << 17) | ((256u / 16) << 24);

static constexpr uint64_t SMEM_DESC_BASE_SW128 =
    (uint64_t(2) << 61) | (uint64_t(1) << 46) | (uint64_t(64) << 32) | (uint64_t(1) << 16);
#define MAKE_SMEM_DESC(base_addr) \
    (SMEM_DESC_BASE_SW128 | ((uint64_t)((base_addr) >> 4) & 0x3FFF))

__device__ __forceinline__ void tc_mma_bf16_cg2(uint32_t d_tmem, uint64_t a_desc,
                                                uint64_t b_desc, uint32_t idesc, bool acc) {
    uint32_t en = acc ? 1u : 0u;
    asm volatile(
        "{ .reg .pred p; setp.ne.u32 p, %5, 0;\n\t"
        "tcgen05.mma.cta_group::2.kind::f16 [%0], %1, %2, %3, "
        "{%4, %4, %4, %4, %4, %4, %4, %4}, p; }"
        :: "r"(d_tmem), "l"(a_desc), "l"(b_desc), "r"(idesc), "r"(0u), "r"(en)
        : "memory");
}
__device__ __forceinline__ void bulk_g2s(uint32_t dst, const void* src,
                                         uint32_t bytes, uint32_t mbar) {
    asm volatile(
        "cp.async.bulk.shared::cta.global.mbarrier::complete_tx::bytes [%0], [%1], %2, [%3];"
        :: "r"(dst), "l"(src), "r"(bytes), "r"(mbar) : "memory");
}
__device__ __forceinline__ uint32_t cluster_rank() {
    uint32_t r;
    asm("mov.u32 %0, %%cluster_ctarank;" : "=r"(r));
    return r;
}
#define TC_ALLOC_CG2(smem_addr, n) \
    asm volatile("tcgen05.alloc.cta_group::2.sync.aligned.shared::cta.b32 [%0], %1;" \
                 :: "r"((uint32_t)(smem_addr)), "r"((uint32_t)(n)) : "memory")
#define TC_RELINQ_CG2() \
    asm volatile("tcgen05.relinquish_alloc_permit.cta_group::2.sync.aligned;")
#define TC_DEALLOC_CG2(tmem, n) \
    asm volatile("tcgen05.dealloc.cta_group::2.sync.aligned.b32 %0, %1;" \
                 :: "r"(tmem), "r"((uint32_t)(n)))
#define TC_COMMIT_MCAST_CG2(mbar, mask) \
    asm volatile("tcgen05.commit.cta_group::2.mbarrier::arrive::one.shared::cluster.multicast::cluster.b64 [%0], %1;" \
                 :: "r"((uint32_t)(mbar)), "h"((uint16_t)(mask)) : "memory")
#define TC_FENCE_AFTER()  asm volatile("tcgen05.fence::after_thread_sync;" ::: "memory")
#define TC_FENCE_BEFORE() asm volatile("tcgen05.fence::before_thread_sync;" ::: "memory")
#define TC_WAIT_LD()      asm volatile("tcgen05.wait::ld.sync.aligned;" ::: "memory")
#define TC_LD_X32(r, addr) \
    asm volatile("tcgen05.ld.sync.aligned.32x32b.x32.b32 " \
        "{%0, %1, %2, %3, %4, %5, %6, %7, %8, %9, %10, %11, %12, %13, %14, %15, " \
        " %16, %17, %18, %19, %20, %21, %22, %23, %24, %25, %26, %27, %28, %29, %30, %31}, [%32];" \
        : "=r"((r)[0]), "=r"((r)[1]), "=r"((r)[2]), "=r"((r)[3]), \
          "=r"((r)[4]), "=r"((r)[5]), "=r"((r)[6]), "=r"((r)[7]), \
          "=r"((r)[8]), "=r"((r)[9]), "=r"((r)[10]), "=r"((r)[11]), \
          "=r"((r)[12]), "=r"((r)[13]), "=r"((r)[14]), "=r"((r)[15]), \
          "=r"((r)[16]), "=r"((r)[17]), "=r"((r)[18]), "=r"((r)[19]), \
          "=r"((r)[20]), "=r"((r)[21]), "=r"((r)[22]), "=r"((r)[23]), \
          "=r"((r)[24]), "=r"((r)[25]), "=r"((r)[26]), "=r"((r)[27]), \
          "=r"((r)[28]), "=r"((r)[29]), "=r"((r)[30]), "=r"((r)[31]) \
        : "r"(addr))
#define MBAR_INIT(mbar, n) \
    asm volatile("mbarrier.init.shared.b64 [%0], %1;" \
                 :: "r"((uint32_t)(mbar)), "r"((uint32_t)(n)) : "memory")
#define MBAR_EXPECT_TX(mbar, bytes) \
    asm volatile("mbarrier.arrive.expect_tx.shared.b64 _, [%0], %1;" \
                 :: "r"((uint32_t)(mbar)), "r"((uint32_t)(bytes)) : "memory")
#define MBAR_ARRIVE_CLUSTER(local_mbar, target_rank) \
    asm volatile("{ .reg .b32 ra; mapa.shared::cluster.u32 ra, %0, %1;\n\t" \
                 "mbarrier.arrive.shared::cluster.b64 _, [ra]; }" \
                 :: "r"((uint32_t)(local_mbar)), "r"((uint32_t)(target_rank)) : "memory")
#define MBAR_INVAL(mbar) \
    asm volatile("mbarrier.inval.shared.b64 [%0];" :: "r"((uint32_t)(mbar)) : "memory")
#define MBAR_WAIT(mbar, parity) do { \
    uint32_t _m = (uint32_t)(mbar), _p = (uint32_t)(parity), _d; \
    asm volatile("{ .reg .pred p; mbarrier.try_wait.parity.acquire.cta.shared::cta.b64 p, [%1], %2; selp.b32 %0, 1, 0, p; }" \
                 : "=r"(_d) : "r"(_m), "r"(_p) : "memory"); \
    if (!_d) { \
        asm volatile("{ .reg .pred P1;\n\tWL_%=:\n\t" \
            "mbarrier.try_wait.parity.acquire.cta.shared::cta.b64 P1, [%0], %1, 0x989680;\n\t" \
            "@P1 bra.uni WD_%=;\n\tbra.uni WL_%=;\n\tWD_%=:\n\t}" \
            :: "r"(_m), "r"(_p) : "memory"); \
    } \
} while (0)
#define FENCE_PROXY() asm volatile("fence.proxy.async.shared::cta;" ::: "memory")
#define CLUSTER_SYNC() do { \
    asm volatile("barrier.cluster.arrive.aligned;" ::: "memory"); \
    asm volatile("barrier.cluster.wait.aligned;" ::: "memory"); \
} while (0)
#endif  // W8A8_TC

__global__ __launch_bounds__(256, 1) __cluster_dims__(2, 1, 1)
void w8a8_tc_kernel(float* __restrict__ out)
{
#if W8A8_TC
    extern __shared__ char dsm[];
    const uint32_t raw    = smem_u32(dsm);
    const uint32_t hdr    = (raw + 1023u) & ~1023u;  // [hdr]=tmem ptr
    const uint32_t full0  = hdr + 16;                // 4 x 8B
    const uint32_t free0  = hdr + 48;                // 4 x 8B
    const uint32_t ready0 = hdr + 80;                // 4 x 8B (rank0 only used)
    const uint32_t fin    = hdr + 112;
    const uint32_t tiles  = hdr + 1024;

    const int tid  = threadIdx.x;
    const int wid  = tid >> 5;
    const int lane = tid & 31;
    const int pair_n = blockIdx.x >> 1;      // 0..7 (N tile of 512)
    const int mt     = blockIdx.y;           // 0..31 (M tile of 256)
    const uint32_t rank = cluster_rank();    // 0/1: M-half of A, N-interleave of B

    if (wid == 0) TC_ALLOC_CG2(hdr, 512);
    if (tid == 0) {
        #pragma unroll
        for (int s = 0; s < NSTAGE; s++) {
            MBAR_INIT(full0 + 8 * s, 1);    // own expect_tx
            MBAR_INIT(free0 + 8 * s, 1);    // one multicast commit arrival
            MBAR_INIT(ready0 + 8 * s, 1);   // rank1 relay arrival
        }
        MBAR_INIT(fin, 1);
    }
    __syncthreads();
    FENCE_PROXY();
    CLUSTER_SYNC();   // peer barriers live before any remote arrive/commit
    uint32_t tmem;
    asm volatile("ld.shared.b32 %0, [%1];" : "=r"(tmem) : "r"(hdr));

    const uint8_t* a_src = g_xt + ((size_t)((mt * 2 + rank) * CHUNKS) << 14);
    const uint8_t* b_src = g_wt + ((size_t)(pair_n * CHUNKS) << 16) + ((size_t)rank << 15);

    if (tid == 0) {
        // ---- producer (both ranks, fully local) ----
        for (int kc = 0; kc < CHUNKS; kc++) {
            const int s = kc & (NSTAGE - 1);
            const int i = kc >> 2;
            if (kc >= NSTAGE) MBAR_WAIT(free0 + 8 * s, (i - 1) & 1);
            MBAR_EXPECT_TX(full0 + 8 * s, STAGE_BYTES);
            bulk_g2s(tiles + s * STAGE_BYTES,        a_src + ((size_t)kc << 14),
                     A_CH, full0 + 8 * s);
            bulk_g2s(tiles + s * STAGE_BYTES + A_CH, b_src + ((size_t)kc << 16),
                     B_CH, full0 + 8 * s);
        }
    } else if (tid == 32 && rank == 1) {
        // ---- relay: local stage full -> arrive on rank0's ready[s] ----
        for (int kc = 0; kc < CHUNKS; kc++) {
            const int s = kc & (NSTAGE - 1);
            const int i = kc >> 2;
            MBAR_WAIT(full0 + 8 * s, i & 1);
            MBAR_ARRIVE_CLUSTER(ready0 + 8 * s, 0);
        }
    } else if (tid == 32 && rank == 0) {
        // ---- consumer: cg2 MMAs for the pair ----
        for (int kc = 0; kc < CHUNKS; kc++) {
            const int s = kc & (NSTAGE - 1);
            const int i = kc >> 2;
            MBAR_WAIT(full0 + 8 * s, i & 1);    // own A/B half staged
            MBAR_WAIT(ready0 + 8 * s, i & 1);   // peer A/B half staged
            const uint64_t ad = MAKE_SMEM_DESC(tiles + s * STAGE_BYTES);
            const bool accb = (kc > 0);
            #pragma unroll
            for (int d = 0; d < 2; d++) {       // two N=256 dispatches
                const uint64_t bd = MAKE_SMEM_DESC(tiles + s * STAGE_BYTES + A_CH + d * 16384);
                #pragma unroll
                for (int st = 0; st < 4; st++)  // K=16 per MMA, +32B = +2 units
                    tc_mma_bf16_cg2(tmem + d * 256, ad + st * 2, bd + st * 2,
                                    TC_IDESC, accb || (st > 0));
            }
            TC_COMMIT_MCAST_CG2(free0 + 8 * s, 0x3);   // release stage in BOTH CTAs
        }
        TC_COMMIT_MCAST_CG2(fin, 0x3);
    }

    // ---- all threads: wait for final MMA, then epilogue ----
    MBAR_WAIT(fin, 0);
    TC_FENCE_AFTER();

    {
        // each CTA owns D rows = its 128 A-rows, 512 cols in its TMEM
        const int sub = wid & 3;                  // TMEM subpartition
        const int nh  = wid >> 2;                 // col half: 0 / 256
        const int row = mt * PAIR_M + (int)rank * 128 + sub * 32 + lane;
        const int cb  = pair_n * PAIR_N + nh * 256;
        float* orow = out + (size_t)row * NDIM + cb;
        const float* bb = g_bf + cb;
        const uint32_t tbase = tmem + nh * 256;

        #pragma unroll
        for (int q = 0; q < 8; q++) {
            uint32_t d[32];
            TC_LD_X32(d, tbase + q * 32);
            TC_WAIT_LD();
            #pragma unroll
            for (int j = 0; j < 8; j++) {
                float4 bj = *(const float4*)(bb + q * 32 + j * 4);
                float4 v;
                v.x = __uint_as_float(d[j * 4 + 0]) + bj.x;
                v.y = __uint_as_float(d[j * 4 + 1]) + bj.y;
                v.z = __uint_as_float(d[j * 4 + 2]) + bj.z;
                v.w = __uint_as_float(d[j * 4 + 3]) + bj.w;
                *(float4*)(orow + q * 32 + j * 4) = v;
            }
        }
        TC_FENCE_BEFORE();
    }

    __syncthreads();
    CLUSTER_SYNC();   // both CTAs done with TMEM + peer-visible barriers
    if (tid == 0) {
        #pragma unroll
        for (int s = 0; s < NSTAGE; s++) {
            MBAR_INVAL(full0 + 8 * s);
            MBAR_INVAL(free0 + 8 * s);
            MBAR_INVAL(ready0 + 8 * s);
        }
        MBAR_INVAL(fin);
    }
    __syncthreads();
    if (wid == 0) {
        TC_RELINQ_CG2();
        TC_DEALLOC_CG2(tmem, 512);
    }
    CLUSTER_SYNC();
#endif  // W8A8_TC
}

// ---------------------------------------------------------------------------
// Launch wrapper: bind by relative size (x > weight > bias); 2 launches.
// ---------------------------------------------------------------------------
extern "C" void kernel_launch(void* const* d_in, const int* in_sizes, int n_in,
                              void* d_out, int out_size)
{
    int idx[3] = {0, 1, 2};
    if (n_in >= 3) {
        for (int a = 0; a < 3; a++)
            for (int b2 = a + 1; b2 < 3; b2++)
                if ((long)in_sizes[idx[b2]] > (long)in_sizes[idx[a]]) {
                    int t = idx[a]; idx[a] = idx[b2]; idx[b2] = t;
                }
    }
    const void* x = d_in[idx[0]];
    const void* w = d_in[idx[1]];
    const void* b = d_in[idx[2]];
    float* out = (float*)d_out;
    (void)out_size;

    cudaFuncSetAttribute(w8a8_tc_kernel,
                         cudaFuncAttributeMaxDynamicSharedMemorySize, TC_SMEM);

    convert_kernel<<<2048, 256>>>(x, w, b);

    dim3 grid(2 * NT8, MT);   // (16, 32) = 512 CTAs = 256 cg2 pairs
    w8a8_tc_kernel<<<grid, 256, TC_SMEM>>>(out);
}

// round 13
// speedup vs baseline: 1.0856x; 1.0382x over previous
#include <cuda_runtime.h>
#include <cuda_bf16.h>
#include <cstdint>

// ---------------------------------------------------------------------------
// W8A8B32O32 Linear: out[8192,4096] = x[8192,4096]i8 @ w[4096,4096]i8^T + bias
//
// R13: persistent cg2 pairs. 74 pairs (148 CTAs, 1/SM) loop over 256 tiles
// of 256(M)x512(N). SMEM stage ring flows across tiles (no per-tile refill),
// epilogue overlaps next tile's staging; TMEM WAR guarded by cluster 'epi'
// barrier. Dedicated producer / consumer+relay warps (320 threads).
// ---------------------------------------------------------------------------
#define TOKENS 8192
#define NDIM   4096
#define KDIM   4096

#define KC 64                     // K elems per chunk (128 B bf16)
#define CHUNKS (KDIM / KC)        // 64
#define PAIR_M 256
#define PAIR_N 512
#define NTILE_M 32                // 8192/256
#define NTILE_N 8                 // 4096/512
#define NTILES  (NTILE_M * NTILE_N)   // 256
#define NSLOT   74

#define A_CH 16384                // 128 rows x 128 B per CTA per chunk
#define B_CH 32768                // 256 rows (2 N-halves) per CTA per chunk
#define STAGE_BYTES (A_CH + B_CH) // 49152
#define NSTAGE 4
#define TC_SMEM (2048 + NSTAGE * STAGE_BYTES)  // 198656

#define THREADS 320               // warps 0-7 epilogue, 8 producer, 9 consumer/relay

#if defined(__CUDA_ARCH_FEAT_SM103_ALL) || defined(__CUDA_ARCH_FEAT_SM100_ALL) || \
    defined(__CUDA_ARCH_SPECIFIC__) || defined(__CUDA_ARCH_FAMILY_SPECIFIC__)
#define W8A8_TC 1
#else
#define W8A8_TC 0
#endif

#define SW128(off) ((off) ^ (((off) >> 3) & 0x70))

// ---- device scratch: pre-tiled, pre-swizzled bf16 operands ----
// A: [mt2(64)][kc(64)] 16KB tiles (128 rows), mt2 = mt*2 + rank
// B: [nt8(8)][kc(64)] 64KB tiles: [rank(2)][half(2)][row(128)][128B]
__device__ __align__(1024) uint8_t g_xt[(size_t)64 * CHUNKS * A_CH];       // 64 MB
__device__ __align__(1024) uint8_t g_wt[(size_t)NTILE_N * CHUNKS * 65536]; // 32 MB
__device__ float g_bf[NDIM];

// ---------------------------------------------------------------------------
// convert: classify dtype, write bf16 pre-tiled scratch
// ---------------------------------------------------------------------------
__device__ int classify16(const uint32_t* p) {
    int fc = 0, ic = 0;
    for (int i = 0; i < 16; i++) {
        uint32_t u = p[i];
        if (((u >> 23) & 0xFF) != 0xFF) {
            float f = __uint_as_float(u);
            if (f == rintf(f) && fabsf(f) <= 4096.0f) fc++;
        }
        int v = (int)u;
        if (v >= -4096 && v <= 4096) ic++;
    }
    if (fc >= 12) return 2;   // float32
    if (ic >= 12) return 1;   // int32
    return 0;                 // packed int8
}

__device__ __forceinline__ void load8f(const void* src, size_t e0, int mode, float* f) {
    if (mode == 0) {
        uint2 r = *(const uint2*)((const int8_t*)src + e0);
        f[0] = (float)(int)(signed char)(r.x);
        f[1] = (float)(int)(signed char)(r.x >> 8);
        f[2] = (float)(int)(signed char)(r.x >> 16);
        f[3] = (float)(int)(signed char)(r.x >> 24);
        f[4] = (float)(int)(signed char)(r.y);
        f[5] = (float)(int)(signed char)(r.y >> 8);
        f[6] = (float)(int)(signed char)(r.y >> 16);
        f[7] = (float)(int)(signed char)(r.y >> 24);
    } else if (mode == 1) {
        int4 a = ((const int4*)src)[e0 / 4];
        int4 b = ((const int4*)src)[e0 / 4 + 1];
        f[0] = (float)a.x; f[1] = (float)a.y; f[2] = (float)a.z; f[3] = (float)a.w;
        f[4] = (float)b.x; f[5] = (float)b.y; f[6] = (float)b.z; f[7] = (float)b.w;
    } else {
        float4 a = ((const float4*)src)[e0 / 4];
        float4 b = ((const float4*)src)[e0 / 4 + 1];
        f[0] = a.x; f[1] = a.y; f[2] = a.z; f[3] = a.w;
        f[4] = b.x; f[5] = b.y; f[6] = b.z; f[7] = b.w;
    }
}

__global__ void convert_kernel(const void* xs, const void* ws, const void* bs) {
    __shared__ int smode[3];
    if (threadIdx.x == 0) {
        smode[0] = classify16((const uint32_t*)xs);
        smode[1] = classify16((const uint32_t*)ws);
        smode[2] = classify16((const uint32_t*)bs);
    }
    __syncthreads();
    const int xm = smode[0], wm = smode[1], bm = smode[2];

    const size_t stride = (size_t)gridDim.x * blockDim.x;
    const size_t t0 = (size_t)blockIdx.x * blockDim.x + threadIdx.x;

    union { uint4 v; __nv_bfloat16 h[8]; } u;
    float f[8];

    const size_t nsegA = (size_t)64 * CHUNKS * 128 * 8;
    for (size_t i = t0; i < nsegA; i += stride) {
        const int seg = (int)(i & 7);
        const int row = (int)((i >> 3) & 127);
        const int t   = (int)(i >> 10);          // mt2*64 + kc
        const int mt2 = t >> 6, kc = t & 63;
        const size_t e0 = ((size_t)(mt2 * 128 + row)) * KDIM + (size_t)kc * KC + seg * 8;
        load8f(xs, e0, xm, f);
        #pragma unroll
        for (int j = 0; j < 8; j++) u.h[j] = __float2bfloat16_rn(f[j]);
        *(uint4*)(g_xt + ((size_t)t << 14) + SW128((uint32_t)(row * 128 + seg * 16))) = u.v;
    }

    const size_t nsegB = (size_t)NTILE_N * CHUNKS * 2 * 2 * 128 * 8;
    for (size_t i = t0; i < nsegB; i += stride) {
        const int seg  = (int)(i & 7);
        const int row  = (int)((i >> 3) & 127);
        const int half = (int)((i >> 10) & 1);
        const int rank = (int)((i >> 11) & 1);
        const int t    = (int)(i >> 12);         // nt8*64 + kc
        const int nt8  = t >> 6, kc = t & 63;
        const int n = nt8 * 512 + half * 256 + rank * 128 + row;
        const size_t e0 = (size_t)n * KDIM + (size_t)kc * KC + seg * 8;
        load8f(ws, e0, wm, f);
        #pragma unroll
        for (int j = 0; j < 8; j++) u.h[j] = __float2bfloat16_rn(f[j]);
        *(uint4*)(g_wt + ((size_t)t << 16) + ((uint32_t)rank << 15) + ((uint32_t)half << 14)
                  + SW128((uint32_t)(row * 128 + seg * 16))) = u.v;
    }

    for (size_t i = t0; i < NDIM; i += stride) {
        if (bm == 2) g_bf[i] = ((const float*)bs)[i];
        else         g_bf[i] = (float)((const int*)bs)[i];
    }
}

// ---------------------------------------------------------------------------
// tcgen05 machinery (arch-specific pass only)
// ---------------------------------------------------------------------------
__device__ __forceinline__ uint32_t smem_u32(const void* p) {
    uint32_t a;
    asm("{ .reg .u64 t; cvta.to.shared.u64 t, %1; cvt.u32.u64 %0, t; }"
        : "=r"(a) : "l"(p));
    return a;
}

#if W8A8_TC
// idesc kind::f16 cg2: dtype F32, a/b BF16, N=256 per dispatch, M_TOTAL=256
static constexpr uint32_t TC_IDESC =
    (1u << 4) | (1u << 7) | (1u << 10) | ((256u / 8) << 17) | ((256u / 16) << 24);

static constexpr uint64_t SMEM_DESC_BASE_SW128 =
    (uint64_t(2) << 61) | (uint64_t(1) << 46) | (uint64_t(64) << 32) | (uint64_t(1) << 16);
#define MAKE_SMEM_DESC(base_addr) \
    (SMEM_DESC_BASE_SW128 | ((uint64_t)((base_addr) >> 4) & 0x3FFF))

__device__ __forceinline__ void tc_mma_bf16_cg2(uint32_t d_tmem, uint64_t a_desc,
                                                uint64_t b_desc, uint32_t idesc, bool acc) {
    uint32_t en = acc ? 1u : 0u;
    asm volatile(
        "{ .reg .pred p; setp.ne.u32 p, %5, 0;\n\t"
        "tcgen05.mma.cta_group::2.kind::f16 [%0], %1, %2, %3, "
        "{%4, %4, %4, %4, %4, %4, %4, %4}, p; }"
        :: "r"(d_tmem), "l"(a_desc), "l"(b_desc), "r"(idesc), "r"(0u), "r"(en)
        : "memory");
}
__device__ __forceinline__ void bulk_g2s(uint32_t dst, const void* src,
                                         uint32_t bytes, uint32_t mbar) {
    asm volatile(
        "cp.async.bulk.shared::cta.global.mbarrier::complete_tx::bytes [%0], [%1], %2, [%3];"
        :: "r"(dst), "l"(src), "r"(bytes), "r"(mbar) : "memory");
}
__device__ __forceinline__ uint32_t cluster_rank() {
    uint32_t r;
    asm("mov.u32 %0, %%cluster_ctarank;" : "=r"(r));
    return r;
}
#define TC_ALLOC_CG2(smem_addr, n) \
    asm volatile("tcgen05.alloc.cta_group::2.sync.aligned.shared::cta.b32 [%0], %1;" \
                 :: "r"((uint32_t)(smem_addr)), "r"((uint32_t)(n)) : "memory")
#define TC_RELINQ_CG2() \
    asm volatile("tcgen05.relinquish_alloc_permit.cta_group::2.sync.aligned;")
#define TC_DEALLOC_CG2(tmem, n) \
    asm volatile("tcgen05.dealloc.cta_group::2.sync.aligned.b32 %0, %1;" \
                 :: "r"(tmem), "r"((uint32_t)(n)))
#define TC_COMMIT_MCAST_CG2(mbar, mask) \
    asm volatile("tcgen05.commit.cta_group::2.mbarrier::arrive::one.shared::cluster.multicast::cluster.b64 [%0], %1;" \
                 :: "r"((uint32_t)(mbar)), "h"((uint16_t)(mask)) : "memory")
#define TC_FENCE_AFTER()  asm volatile("tcgen05.fence::after_thread_sync;" ::: "memory")
#define TC_FENCE_BEFORE() asm volatile("tcgen05.fence::before_thread_sync;" ::: "memory")
#define TC_WAIT_LD()      asm volatile("tcgen05.wait::ld.sync.aligned;" ::: "memory")
#define TC_LD_X32(r, addr) \
    asm volatile("tcgen05.ld.sync.aligned.32x32b.x32.b32 " \
        "{%0, %1, %2, %3, %4, %5, %6, %7, %8, %9, %10, %11, %12, %13, %14, %15, " \
        " %16, %17, %18, %19, %20, %21, %22, %23, %24, %25, %26, %27, %28, %29, %30, %31}, [%32];" \
        : "=r"((r)[0]), "=r"((r)[1]), "=r"((r)[2]), "=r"((r)[3]), \
          "=r"((r)[4]), "=r"((r)[5]), "=r"((r)[6]), "=r"((r)[7]), \
          "=r"((r)[8]), "=r"((r)[9]), "=r"((r)[10]), "=r"((r)[11]), \
          "=r"((r)[12]), "=r"((r)[13]), "=r"((r)[14]), "=r"((r)[15]), \
          "=r"((r)[16]), "=r"((r)[17]), "=r"((r)[18]), "=r"((r)[19]), \
          "=r"((r)[20]), "=r"((r)[21]), "=r"((r)[22]), "=r"((r)[23]), \
          "=r"((r)[24]), "=r"((r)[25]), "=r"((r)[26]), "=r"((r)[27]), \
          "=r"((r)[28]), "=r"((r)[29]), "=r"((r)[30]), "=r"((r)[31]) \
        : "r"(addr))
#define MBAR_INIT(mbar, n) \
    asm volatile("mbarrier.init.shared.b64 [%0], %1;" \
                 :: "r"((uint32_t)(mbar)), "r"((uint32_t)(n)) : "memory")
#define MBAR_EXPECT_TX(mbar, bytes) \
    asm volatile("mbarrier.arrive.expect_tx.shared.b64 _, [%0], %1;" \
                 :: "r"((uint32_t)(mbar)), "r"((uint32_t)(bytes)) : "memory")
#define MBAR_ARRIVE(mbar) \
    asm volatile("mbarrier.arrive.shared.b64 _, [%0];" \
                 :: "r"((uint32_t)(mbar)) : "memory")
#define MBAR_ARRIVE_CLUSTER(local_mbar, target_rank) \
    asm volatile("{ .reg .b32 ra; mapa.shared::cluster.u32 ra, %0, %1;\n\t" \
                 "mbarrier.arrive.shared::cluster.b64 _, [ra]; }" \
                 :: "r"((uint32_t)(local_mbar)), "r"((uint32_t)(target_rank)) : "memory")
#define MBAR_INVAL(mbar) \
    asm volatile("mbarrier.inval.shared.b64 [%0];" :: "r"((uint32_t)(mbar)) : "memory")
#define MBAR_WAIT(mbar, parity) do { \
    uint32_t _m = (uint32_t)(mbar), _p = (uint32_t)(parity), _d; \
    asm volatile("{ .reg .pred p; mbarrier.try_wait.parity.acquire.cta.shared::cta.b64 p, [%1], %2; selp.b32 %0, 1, 0, p; }" \
                 : "=r"(_d) : "r"(_m), "r"(_p) : "memory"); \
    if (!_d) { \
        asm volatile("{ .reg .pred P1;\n\tWL_%=:\n\t" \
            "mbarrier.try_wait.parity.acquire.cta.shared::cta.b64 P1, [%0], %1, 0x989680;\n\t" \
            "@P1 bra.uni WD_%=;\n\tbra.uni WL_%=;\n\tWD_%=:\n\t}" \
            :: "r"(_m), "r"(_p) : "memory"); \
    } \
} while (0)
#define FENCE_PROXY() asm volatile("fence.proxy.async.shared::cta;" ::: "memory")
#define CLUSTER_SYNC() do { \
    asm volatile("barrier.cluster.arrive.aligned;" ::: "memory"); \
    asm volatile("barrier.cluster.wait.aligned;" ::: "memory"); \
} while (0)
#endif  // W8A8_TC

__global__ __launch_bounds__(THREADS, 1) __cluster_dims__(2, 1, 1)
void w8a8_tc_kernel(float* __restrict__ out)
{
#if W8A8_TC
    extern __shared__ char dsm[];
    const uint32_t raw    = smem_u32(dsm);
    const uint32_t hdr    = (raw + 1023u) & ~1023u;  // [hdr]=tmem ptr
    const uint32_t full0  = hdr + 16;                // 4 x 8B
    const uint32_t free0  = hdr + 48;                // 4 x 8B
    const uint32_t ready0 = hdr + 80;                // 4 x 8B (rank0 used)
    const uint32_t fin    = hdr + 112;
    const uint32_t epib   = hdr + 120;               // epi-done (rank0, count 2)
    const uint32_t tiles  = hdr + 1024;

    const int tid  = threadIdx.x;
    const int wid  = tid >> 5;
    const int lane = tid & 31;
    const int slot = blockIdx.y;             // 0..73
    const uint32_t rank = cluster_rank();    // 0/1

    const int count = (slot < NTILES - 3 * NSLOT) ? 4 : 3;   // slot<34 ? 4 : 3

    if (wid == 0) TC_ALLOC_CG2(hdr, 512);
    if (tid == 0) {
        #pragma unroll
        for (int s = 0; s < NSTAGE; s++) {
            MBAR_INIT(full0 + 8 * s, 1);
            MBAR_INIT(free0 + 8 * s, 1);
            MBAR_INIT(ready0 + 8 * s, 1);
        }
        MBAR_INIT(fin, 1);
        MBAR_INIT(epib, 2);
    }
    __syncthreads();
    FENCE_PROXY();
    CLUSTER_SYNC();
    uint32_t tmem;
    asm volatile("ld.shared.b32 %0, [%1];" : "=r"(tmem) : "r"(hdr));

    if (wid == 8) {
        // =================== PRODUCER (one thread, both ranks) ===============
        if (lane == 0) {
            int g = 0;
            for (int it = 0; it < count; it++) {
                const int t  = slot + NSLOT * it;
                const int mt = t & (NTILE_M - 1);
                const int pn = t >> 5;
                const uint8_t* a_src = g_xt + ((size_t)((mt * 2 + (int)rank) * CHUNKS) << 14);
                const uint8_t* b_src = g_wt + ((size_t)(pn * CHUNKS) << 16) + ((size_t)rank << 15);
                for (int kc = 0; kc < CHUNKS; kc++, g++) {
                    const int s = g & (NSTAGE - 1);
                    if (g >= NSTAGE) MBAR_WAIT(free0 + 8 * s, ((g >> 2) - 1) & 1);
                    MBAR_EXPECT_TX(full0 + 8 * s, STAGE_BYTES);
                    bulk_g2s(tiles + s * STAGE_BYTES,        a_src + ((size_t)kc << 14),
                             A_CH, full0 + 8 * s);
                    bulk_g2s(tiles + s * STAGE_BYTES + A_CH, b_src + ((size_t)kc << 16),
                             B_CH, full0 + 8 * s);
                }
            }
        }
    } else if (wid == 9) {
        if (lane == 0 && rank == 1) {
            // ============ RELAY: local full -> rank0 ready ==================
            int g = 0;
            for (int it = 0; it < count; it++)
                for (int kc = 0; kc < CHUNKS; kc++, g++) {
                    const int s = g & (NSTAGE - 1);
                    MBAR_WAIT(full0 + 8 * s, (g >> 2) & 1);
                    MBAR_ARRIVE_CLUSTER(ready0 + 8 * s, 0);
                }
        } else if (lane == 0 && rank == 0) {
            // ============ CONSUMER: cg2 MMAs ================================
            int g = 0;
            for (int it = 0; it < count; it++) {
                if (it > 0) MBAR_WAIT(epib, (it - 1) & 1);   // TMEM free (both CTAs)
                for (int kc = 0; kc < CHUNKS; kc++, g++) {
                    const int s = g & (NSTAGE - 1);
                    const int ph = (g >> 2) & 1;
                    MBAR_WAIT(full0 + 8 * s, ph);
                    MBAR_WAIT(ready0 + 8 * s, ph);
                    const uint64_t ad = MAKE_SMEM_DESC(tiles + s * STAGE_BYTES);
                    const bool accb = (kc > 0);
                    #pragma unroll
                    for (int d = 0; d < 2; d++) {
                        const uint64_t bd =
                            MAKE_SMEM_DESC(tiles + s * STAGE_BYTES + A_CH + d * 16384);
                        #pragma unroll
                        for (int st = 0; st < 4; st++)
                            tc_mma_bf16_cg2(tmem + d * 256, ad + st * 2, bd + st * 2,
                                            TC_IDESC, accb || (st > 0));
                    }
                    TC_COMMIT_MCAST_CG2(free0 + 8 * s, 0x3);
                }
                TC_COMMIT_MCAST_CG2(fin, 0x3);   // tile's MMAs retired -> fin flips
            }
        }
    } else {
        // =================== EPILOGUE (warps 0-7) ============================
        const int sub = wid & 3;
        const int nh  = wid >> 2;
        for (int it = 0; it < count; it++) {
            const int t  = slot + NSLOT * it;
            const int mt = t & (NTILE_M - 1);
            const int pn = t >> 5;

            MBAR_WAIT(fin, it & 1);
            TC_FENCE_AFTER();

            const int row = mt * PAIR_M + (int)rank * 128 + sub * 32 + lane;
            const int cb  = pn * PAIR_N + nh * 256;
            float* orow = out + (size_t)row * NDIM + cb;
            const float* bb = g_bf + cb;
            const uint32_t tbase = tmem + nh * 256;

            #pragma unroll
            for (int q = 0; q < 8; q++) {
                uint32_t d[32];
                TC_LD_X32(d, tbase + q * 32);
                TC_WAIT_LD();
                #pragma unroll
                for (int j = 0; j < 8; j++) {
                    float4 bj = *(const float4*)(bb + q * 32 + j * 4);
                    float4 v;
                    v.x = __uint_as_float(d[j * 4 + 0]) + bj.x;
                    v.y = __uint_as_float(d[j * 4 + 1]) + bj.y;
                    v.z = __uint_as_float(d[j * 4 + 2]) + bj.z;
                    v.w = __uint_as_float(d[j * 4 + 3]) + bj.w;
                    *(float4*)(orow + q * 32 + j * 4) = v;
                }
            }
            TC_FENCE_BEFORE();

            // all 8 epilogue warps done reading TMEM for this tile
            asm volatile("bar.sync 1, 256;" ::: "memory");
            if (tid == 0) {
                if (rank == 0) MBAR_ARRIVE(epib);
                else           MBAR_ARRIVE_CLUSTER(epib, 0);
            }
        }
    }

    __syncthreads();
    CLUSTER_SYNC();
    if (tid == 0) {
        #pragma unroll
        for (int s = 0; s < NSTAGE; s++) {
            MBAR_INVAL(full0 + 8 * s);
            MBAR_INVAL(free0 + 8 * s);
            MBAR_INVAL(ready0 + 8 * s);
        }
        MBAR_INVAL(fin);
        MBAR_INVAL(epib);
    }
    __syncthreads();
    if (wid == 0) {
        TC_RELINQ_CG2();
        TC_DEALLOC_CG2(tmem, 512);
    }
    CLUSTER_SYNC();
#endif  // W8A8_TC
}

// ---------------------------------------------------------------------------
// Launch wrapper: bind by relative size (x > weight > bias); 2 launches.
// ---------------------------------------------------------------------------
extern "C" void kernel_launch(void* const* d_in, const int* in_sizes, int n_in,
                              void* d_out, int out_size)
{
    int idx[3] = {0, 1, 2};
    if (n_in >= 3) {
        for (int a = 0; a < 3; a++)
            for (int b2 = a + 1; b2 < 3; b2++)
                if ((long)in_sizes[idx[b2]] > (long)in_sizes[idx[a]]) {
                    int t = idx[a]; idx[a] = idx[b2]; idx[b2] = t;
                }
    }
    const void* x = d_in[idx[0]];
    const void* w = d_in[idx[1]];
    const void* b = d_in[idx[2]];
    float* out = (float*)d_out;
    (void)out_size;

    cudaFuncSetAttribute(w8a8_tc_kernel,
                         cudaFuncAttributeMaxDynamicSharedMemorySize, TC_SMEM);

    convert_kernel<<<2048, 256>>>(x, w, b);

    dim3 grid(2, NSLOT);   // 148 CTAs = 74 persistent cg2 pairs
    w8a8_tc_kernel<<<grid, THREADS, TC_SMEM>>>(out);
}